// round 4
// baseline (speedup 1.0000x reference)
#include <cuda_runtime.h>
#include <cstdint>

// Scratch: per-node accumulators (c4, s4, deg, pad) + scalar partials + done ticket.
// __device__ globals are zero-initialized at module load; node_kernel re-zeros
// everything it consumes, so the pipeline is self-cleaning across graph replays
// and needs no separate zero pass.
#define MAX_NODES 100000
__device__ float4   g_acc[MAX_NODES];
__device__ float    g_part[2];   // [0] = pair_loss_sum, [1] = n_pairs
__device__ unsigned g_done;

__device__ __forceinline__ void red_v4(float4* addr, float a, float b, float c, float d) {
    asm volatile("red.global.add.v4.f32 [%0], {%1, %2, %3, %4};"
                 :: "l"(addr), "f"(a), "f"(b), "f"(c), "f"(d)
                 : "memory");
}

__device__ __forceinline__ void edge_contrib(int s, int t, float2 ps, float2 pt) {
    float dx = pt.x - ps.x;
    float dy = pt.y - ps.y;
    float nrm = sqrtf(fmaf(dx, dx, dy * dy));
    float inv = 1.0f / fmaxf(nrm, 1e-8f);
    float u = dx * inv, v = dy * inv;
    // cos(2t) = u^2 - v^2 ; sin(2t) = 2uv ; double-angle again for 4t.
    float a = u * u - v * v;
    float b = 2.0f * u * v;
    float c4 = a * a - b * b;
    float s4 = 2.0f * a * b;
    // 4-theta terms are invariant under d -> -d: identical payload to both endpoints.
    red_v4(&g_acc[s], c4, s4, 1.0f, 0.0f);
    red_v4(&g_acc[t], c4, s4, 1.0f, 0.0f);
}

// Vectorized path: 4 edges per thread, int4 index loads, 8 gathers in flight
// before the 8 REDs. Requires E % 4 == 0 (so ei + E stays 16B-aligned).
__global__ void edge_kernel_v4(const float* __restrict__ pos,
                               const int*   __restrict__ ei,
                               int E) {
    int base = (blockIdx.x * blockDim.x + threadIdx.x) * 4;
    if (base >= E) return;
    int4 si = *(const int4*)(ei + base);
    int4 ti = *(const int4*)(ei + E + base);
    const float2* p2 = (const float2*)pos;
    float2 ps0 = __ldg(p2 + si.x), pt0 = __ldg(p2 + ti.x);
    float2 ps1 = __ldg(p2 + si.y), pt1 = __ldg(p2 + ti.y);
    float2 ps2 = __ldg(p2 + si.z), pt2 = __ldg(p2 + ti.z);
    float2 ps3 = __ldg(p2 + si.w), pt3 = __ldg(p2 + ti.w);
    edge_contrib(si.x, ti.x, ps0, pt0);
    edge_contrib(si.y, ti.y, ps1, pt1);
    edge_contrib(si.z, ti.z, ps2, pt2);
    edge_contrib(si.w, ti.w, ps3, pt3);
}

__global__ void edge_kernel_scalar(const float* __restrict__ pos,
                                   const int*   __restrict__ ei,
                                   int E) {
    int e = blockIdx.x * blockDim.x + threadIdx.x;
    if (e >= E) return;
    int s = ei[e];
    int t = ei[E + e];
    const float2* p2 = (const float2*)pos;
    edge_contrib(s, t, __ldg(p2 + s), __ldg(p2 + t));
}

__global__ void node_kernel(int n, float* __restrict__ out) {
    int i = blockIdx.x * blockDim.x + threadIdx.x;
    float pl = 0.0f, np = 0.0f;
    if (i < n) {
        float4 acc = g_acc[i];
        g_acc[i] = make_float4(0.f, 0.f, 0.f, 0.f);   // self-clean for next replay
        float k = acc.z;
        // sum_{i<j}(dot^2 - dot^4) = (k^2 - C4^2 - S4^2)/16  (includes the 0.5 pair factor)
        pl = (k * k - (acc.x * acc.x + acc.y * acc.y)) * 0.0625f;
        np = 0.5f * k * (k - 1.0f);
    }
    #pragma unroll
    for (int o = 16; o > 0; o >>= 1) {
        pl += __shfl_down_sync(0xffffffffu, pl, o);
        np += __shfl_down_sync(0xffffffffu, np, o);
    }
    __shared__ float s_pl[32];
    __shared__ float s_np[32];
    int lane = threadIdx.x & 31;
    int wid  = threadIdx.x >> 5;
    if (lane == 0) { s_pl[wid] = pl; s_np[wid] = np; }
    __syncthreads();
    if (wid == 0) {
        int nw = (blockDim.x + 31) >> 5;
        pl = (lane < nw) ? s_pl[lane] : 0.0f;
        np = (lane < nw) ? s_np[lane] : 0.0f;
        #pragma unroll
        for (int o = 16; o > 0; o >>= 1) {
            pl += __shfl_down_sync(0xffffffffu, pl, o);
            np += __shfl_down_sync(0xffffffffu, np, o);
        }
        if (lane == 0) {
            atomicAdd(&g_part[0], pl);
            atomicAdd(&g_part[1], np);
            __threadfence();
            unsigned done = atomicAdd(&g_done, 1u);
            if (done == gridDim.x - 1) {
                // last block: all partials visible after the fence/atomic chain
                float a = atomicAdd(&g_part[0], 0.0f);
                float b = atomicAdd(&g_part[1], 0.0f);
                out[0] = a / fmaxf(b, 1.0f);
                // self-clean scalars for the next replay
                g_part[0] = 0.f;
                g_part[1] = 0.f;
                g_done = 0u;
            }
        }
    }
}

extern "C" void kernel_launch(void* const* d_in, const int* in_sizes, int n_in,
                              void* d_out, int out_size) {
    const float* pos = (const float*)d_in[0];
    const int*   ei  = (const int*)d_in[2];
    int N = in_sizes[0] / 2;      // node_positions: (1, N, 2)
    int E = in_sizes[2] / 2;      // edge_index: (2, E)

    const int TB = 256;
    if ((E & 3) == 0) {
        int nth = E / 4;
        edge_kernel_v4<<<(nth + TB - 1) / TB, TB>>>(pos, ei, E);
    } else {
        edge_kernel_scalar<<<(E + TB - 1) / TB, TB>>>(pos, ei, E);
    }
    node_kernel<<<(N + TB - 1) / TB, TB>>>(N, (float*)d_out);
}